// round 15
// baseline (speedup 1.0000x reference)
#include <cuda_runtime.h>
#include <cuda_bf16.h>
#include <mma.h>
#include <math.h>
#include <stdint.h>
#include <type_traits>

using namespace nvcuda;

#define Bb_ 4
#define S_ 1024
#define HID_ 4096
#define NH_ 32
#define HD_ 128
#define O3_ 12288
#define R_ 32
#define SCALE_ 0.08838834764831845f

typedef __nv_bfloat16 bf16;

// RULES (hard-won): device globals referenced ONLY inside kernel bodies.
// No tcgen05 (harness virtual arch compute_103 rejects 'a' features).
// All smem row strides MUST be 16B multiples (R7 lesson).

// ---- proven 6-symbol buffer set ----
__device__ float g_qkv[(size_t)Bb_ * S_ * O3_];        // fp32 qkv; q-region reused for planar V
__device__ float g_mid[Bb_ * S_ * R_];                 // grouped bf16 mid
__device__ float g_q[(size_t)Bb_ * NH_ * S_ * HD_];    // grouped bf16 q
__device__ float g_k[(size_t)Bb_ * NH_ * S_ * HD_];    // grouped k; later wd presplit
__device__ float g_scores[(size_t)Bb_ * NH_ * S_ * S_];// wq presplit -> scores -> grouped probs
__device__ float g_attn[(size_t)Bb_ * S_ * HID_];      // hs presplit -> fp32 attn

// Grouped-split layout (bf16 view): fp32 elem e -> hi at 8(e/4)+e%4, lo at +4.

__device__ __forceinline__ void split1(float x, bf16& h, bf16& l) {
    h = __float2bfloat16(x);
    l = __float2bfloat16(x - __bfloat162float(h));
}
__device__ __forceinline__ void split4store(float4 v, bf16* hp, bf16* lp) {
    bf16 h0, h1, h2, h3, l0, l1, l2, l3;
    split1(v.x, h0, l0); split1(v.y, h1, l1);
    split1(v.z, h2, l2); split1(v.w, h3, l3);
    __nv_bfloat162 a, b, c, d;
    a.x = h0; a.y = h1; b.x = h2; b.y = h3;
    c.x = l0; c.y = l1; d.x = l2; d.y = l3;
    *reinterpret_cast<__nv_bfloat162*>(hp)     = a;
    *reinterpret_cast<__nv_bfloat162*>(hp + 2) = b;
    *reinterpret_cast<__nv_bfloat162*>(lp)     = c;
    *reinterpret_cast<__nv_bfloat162*>(lp + 2) = d;
}
__device__ __forceinline__ uint4 split4pack(float4 v) {
    bf16 h0, h1, h2, h3, l0, l1, l2, l3;
    split1(v.x, h0, l0); split1(v.y, h1, l1);
    split1(v.z, h2, l2); split1(v.w, h3, l3);
    __nv_bfloat162 a, b, c, d;
    a.x = h0; a.y = h1; b.x = h2; b.y = h3;
    c.x = l0; c.y = l1; d.x = l2; d.y = l3;
    uint4 r;
    r.x = *reinterpret_cast<uint32_t*>(&a);
    r.y = *reinterpret_cast<uint32_t*>(&b);
    r.z = *reinterpret_cast<uint32_t*>(&c);
    r.w = *reinterpret_cast<uint32_t*>(&d);
    return r;
}

// ======== BK=32 pipelined wmma split GEMM core (strides 40/136 = 16B mult) ========
// AMODE: 0 = fp32 rows (in-loop split), 1 = grouped-presplit bf16 rows
// BMODE: 1 = NT grouped-presplit, 3 = K-major planar presplit (Bv=H, Bv2=L)
// LORA tail = ONE extra BK=32 iteration (R_=32): A from grouped mid, B from fp32 lora.
#define SSTR 40   // smem row stride (elems) for 32-K tiles: 80B = 5x16B
template <int AMODE, int BMODE, int LORA, int SCALEOUT>
__device__ __forceinline__ void gemm32(
    const void* __restrict__ Av, const int lda,
    const void* __restrict__ Bv, const void* __restrict__ Bv2, const int ldb,
    float* __restrict__ C, const int ldc,
    const int klim, const int bm, const int bn,
    const void* __restrict__ midv, const float* __restrict__ lorav)
{
    extern __shared__ __align__(16) bf16 dsm[];
    bf16* smA = dsm;                                   // [2][2][128][SSTR]
    bf16* smB = dsm + 2 * 2 * 128 * SSTR;              // NT: [2][2][128][SSTR]; PV: [2][2][32][136]
    constexpr int BSTG = (BMODE == 3) ? (32 * 136) : (128 * SSTR);

    const int t = threadIdx.x;
    const int warp = t >> 5;
    const int wm = warp >> 2, wn = warp & 3;

    wmma::fragment<wmma::accumulator, 16, 16, 16, float> cfr[4][2];
#pragma unroll
    for (int mi = 0; mi < 4; mi++)
#pragma unroll
        for (int ni = 0; ni < 2; ni++) wmma::fill_fragment(cfr[mi][ni], 0.0f);

    const int kT = klim >> 5;
    const int total = kT + (LORA ? 1 : 0);

    uint4  uA[4], uB[4];
    float4 fA[4], fB[4];

    auto loadA = [&](int tt) {
        const bool tail = LORA && (tt >= kT);
        const int k0 = tt << 5;
#pragma unroll
        for (int i = 0; i < 4; i++) {
            int idx = i * 256 + t;
            int row = idx >> 3, q8 = idx & 7;          // 8 groups of 4 elems per 32-K row
            if (AMODE == 1) {
                const bf16* src = tail
                    ? ((const bf16*)midv + (size_t)(bm * 128 + row) * (2 * R_) + 2 * (q8 * 4))
                    : ((const bf16*)Av + (size_t)(bm * 128 + row) * (2 * lda) + 2 * (k0 + q8 * 4));
                uA[i] = *reinterpret_cast<const uint4*>(src);
            } else {
                fA[i] = *reinterpret_cast<const float4*>(
                    (const float*)Av + (size_t)(bm * 128 + row) * lda + k0 + q8 * 4);
            }
        }
    };
    auto storeA = [&](int st) {
#pragma unroll
        for (int i = 0; i < 4; i++) {
            int idx = i * 256 + t;
            int row = idx >> 3, q8 = idx & 7;
            bf16* h = smA + ((st * 2 + 0) * 128 + row) * SSTR + q8 * 4;
            bf16* l = smA + ((st * 2 + 1) * 128 + row) * SSTR + q8 * 4;
            if (AMODE == 1) {
                *reinterpret_cast<uint2*>(h) = make_uint2(uA[i].x, uA[i].y);
                *reinterpret_cast<uint2*>(l) = make_uint2(uA[i].z, uA[i].w);
            } else {
                split4store(fA[i], h, l);
            }
        }
    };
    auto loadB = [&](int tt) {
        const bool tail = LORA && (tt >= kT);
        const int k0 = tt << 5;
#pragma unroll
        for (int i = 0; i < 4; i++) {
            int idx = i * 256 + t;
            if (BMODE == 1) {
                int row = idx >> 3, q8 = idx & 7;
                if (tail) {
                    fB[i] = *reinterpret_cast<const float4*>(
                        lorav + (size_t)(bn * 128 + row) * R_ + q8 * 4);
                } else {
                    const bf16* src = (const bf16*)Bv
                        + (size_t)(bn * 128 + row) * (2 * ldb) + 2 * (k0 + q8 * 4);
                    uB[i] = *reinterpret_cast<const uint4*>(src);
                }
            } else {  // BMODE 3: K-major planar
                int kr = idx >> 5, nc = (idx & 31) * 4;
                uint2 vh = *reinterpret_cast<const uint2*>(
                    (const bf16*)Bv + (size_t)(k0 + kr) * ldb + nc);
                uint2 vl = *reinterpret_cast<const uint2*>(
                    (const bf16*)Bv2 + (size_t)(k0 + kr) * ldb + nc);
                uB[i] = make_uint4(vh.x, vh.y, vl.x, vl.y);
            }
        }
    };
    auto storeB = [&](int st, int tt) {
        const bool tail = LORA && (tt >= kT);
#pragma unroll
        for (int i = 0; i < 4; i++) {
            int idx = i * 256 + t;
            if (BMODE == 1) {
                int row = idx >> 3, q8 = idx & 7;
                bf16* h = smB + (st * 2 + 0) * BSTG + row * SSTR + q8 * 4;
                bf16* l = smB + (st * 2 + 1) * BSTG + row * SSTR + q8 * 4;
                if (tail) {
                    split4store(fB[i], h, l);
                } else {
                    *reinterpret_cast<uint2*>(h) = make_uint2(uB[i].x, uB[i].y);
                    *reinterpret_cast<uint2*>(l) = make_uint2(uB[i].z, uB[i].w);
                }
            } else {
                int kr = idx >> 5, nc = (idx & 31) * 4;
                *reinterpret_cast<uint2*>(smB + (st * 2 + 0) * BSTG + kr * 136 + nc) =
                    make_uint2(uB[i].x, uB[i].y);
                *reinterpret_cast<uint2*>(smB + (st * 2 + 1) * BSTG + kr * 136 + nc) =
                    make_uint2(uB[i].z, uB[i].w);
            }
        }
    };

    using BLay = typename std::conditional<BMODE == 3, wmma::row_major, wmma::col_major>::type;

    auto compute = [&](int st, int ks) {
        wmma::fragment<wmma::matrix_b, 16, 16, 16, bf16, BLay> bH[2], bL[2];
#pragma unroll
        for (int ni = 0; ni < 2; ni++) {
            if (BMODE == 3) {
                int base = (ks * 16) * 136 + wn * 32 + ni * 16;
                wmma::load_matrix_sync(bH[ni], smB + (st * 2 + 0) * BSTG + base, 136);
                wmma::load_matrix_sync(bL[ni], smB + (st * 2 + 1) * BSTG + base, 136);
            } else {
                int base = (wn * 32 + ni * 16) * SSTR + ks * 16;
                wmma::load_matrix_sync(bH[ni], smB + (st * 2 + 0) * BSTG + base, SSTR);
                wmma::load_matrix_sync(bL[ni], smB + (st * 2 + 1) * BSTG + base, SSTR);
            }
        }
#pragma unroll
        for (int mi = 0; mi < 4; mi++) {
            wmma::fragment<wmma::matrix_a, 16, 16, 16, bf16, wmma::row_major> aH, aL;
            int base = (wm * 64 + mi * 16) * SSTR + ks * 16;
            wmma::load_matrix_sync(aH, smA + (0 * 128 * SSTR) + st * (2 * 128 * SSTR) + base, SSTR);
            wmma::load_matrix_sync(aL, smA + (1 * 128 * SSTR) + st * (2 * 128 * SSTR) + base, SSTR);
#pragma unroll
            for (int ni = 0; ni < 2; ni++) {
                wmma::mma_sync(cfr[mi][ni], aH, bH[ni], cfr[mi][ni]);
                wmma::mma_sync(cfr[mi][ni], aH, bL[ni], cfr[mi][ni]);
                wmma::mma_sync(cfr[mi][ni], aL, bH[ni], cfr[mi][ni]);
            }
        }
    };

    loadA(0); storeA(0);
    loadB(0); storeB(0, 0);
    __syncthreads();

    for (int tt = 0; tt < total; tt++) {
        const int st = tt & 1, nx = st ^ 1;
        const bool nxt = (tt + 1 < total);
        if (nxt) loadA(tt + 1);
        compute(st, 0);
        if (nxt) { storeA(nx); loadB(tt + 1); }
        compute(st, 1);
        if (nxt) storeB(nx, tt + 1);
        __syncthreads();
    }

#pragma unroll
    for (int mi = 0; mi < 4; mi++)
#pragma unroll
        for (int ni = 0; ni < 2; ni++) {
            if (SCALEOUT) {
#pragma unroll
                for (int e = 0; e < cfr[mi][ni].num_elements; e++) cfr[mi][ni].x[e] *= SCALE_;
            }
            wmma::store_matrix_sync(
                C + (size_t)(bm * 128 + wm * 64 + mi * 16) * ldc + bn * 128 + wn * 32 + ni * 16,
                cfr[mi][ni], ldc, wmma::mem_row_major);
        }
}

#define SMEM_NT ((2 * 2 * 128 * SSTR + 2 * 2 * 128 * SSTR) * 2)   // 81920 B
#define SMEM_PV ((2 * 2 * 128 * SSTR + 2 * 2 * 32 * 136) * 2)     // 75776 B

// ---------------- GEMM wrapper kernels ----------------
__global__ __launch_bounds__(256, 2) void k_qkv(const float* __restrict__ lora_out)
{
    const int b = (int)(blockIdx.y >> 3);
    gemm32<1, 1, 1, 0>(g_attn, HID_, g_scores, nullptr, HID_, g_qkv, O3_, HID_,
                       blockIdx.y, blockIdx.x,
                       g_mid, lora_out + (size_t)b * O3_ * R_);
}

__global__ __launch_bounds__(256, 2) void k_scores()
{
    const int ti = (int)blockIdx.x;                // lower-triangle tile index [0,36)
    int bm = (int)((sqrtf(8.f * ti + 1.f) - 1.f) * 0.5f);
    while ((bm + 1) * (bm + 2) / 2 <= ti) ++bm;
    while (bm * (bm + 1) / 2 > ti) --bm;
    const int bn = ti - bm * (bm + 1) / 2;
    const size_t z = blockIdx.y;
    gemm32<1, 1, 0, 1>(g_q + z * S_ * HD_, HD_, g_k + z * S_ * HD_, nullptr, HD_,
                       g_scores + z * S_ * S_, S_, HD_,
                       bm, bn, nullptr, nullptr);
}

__global__ __launch_bounds__(256, 2) void k_pv()
{
    const size_t z = blockIdx.y;
    const int b = (int)(z >> 5), h = (int)(z & 31);
    const int bm = (int)blockIdx.x;
    const int klim = (bm + 1) * 128;
    const bf16* vbase = reinterpret_cast<const bf16*>(g_qkv + (size_t)b * S_ * O3_);
    gemm32<1, 3, 0, 0>(g_scores + z * S_ * S_, S_,
                       vbase + h * HD_, vbase + HID_ + h * HD_, 2 * O3_,
                       g_attn + (size_t)b * S_ * HID_ + h * HD_, HID_,
                       klim, bm, 0, nullptr, nullptr);
}

__global__ __launch_bounds__(256, 2) void k_dense(float* __restrict__ out)
{
    gemm32<0, 1, 0, 0>(g_attn, HID_, g_k, nullptr, HID_, out, HID_, HID_,
                       blockIdx.y, blockIdx.x, nullptr, nullptr);
}

// ---------------- split kernels (dst globals INSIDE) ----------------
__global__ __launch_bounds__(256) void split_hs_kernel(const float* __restrict__ s)
{
    size_t e = ((size_t)blockIdx.x * 256 + threadIdx.x) * 4;
    float4 v = *reinterpret_cast<const float4*>(s + e);
    *reinterpret_cast<uint4*>(reinterpret_cast<bf16*>(g_attn) + 2 * e) = split4pack(v);
}
__global__ __launch_bounds__(256) void split_wq_kernel(const float* __restrict__ s)
{
    size_t e = ((size_t)blockIdx.x * 256 + threadIdx.x) * 4;
    float4 v = *reinterpret_cast<const float4*>(s + e);
    *reinterpret_cast<uint4*>(reinterpret_cast<bf16*>(g_scores) + 2 * e) = split4pack(v);
}
__global__ __launch_bounds__(256) void split_wd_kernel(const float* __restrict__ s)
{
    size_t e = ((size_t)blockIdx.x * 256 + threadIdx.x) * 4;
    float4 v = *reinterpret_cast<const float4*>(s + e);
    *reinterpret_cast<uint4*>(reinterpret_cast<bf16*>(g_k) + 2 * e) = split4pack(v);
}

// ---------------- small kernels ----------------
__global__ __launch_bounds__(256) void lora_mid_kernel(
    const float* __restrict__ hs, const float* __restrict__ lin)
{
    const int row = blockIdx.x;
    const int b = row / S_;
    __shared__ float sh[HID_];
    for (int i = threadIdx.x; i < HID_; i += 256) sh[i] = hs[(size_t)row * HID_ + i];
    __syncthreads();
    const int warp = threadIdx.x >> 5, lane = threadIdx.x & 31;
    for (int r = warp; r < R_; r += 8) {
        const float* lrow = lin + ((size_t)b * R_ + r) * HID_;
        float acc = 0.f;
        for (int i = lane * 4; i < HID_; i += 128) {
            float4 a = *reinterpret_cast<const float4*>(&sh[i]);
            float4 w = *reinterpret_cast<const float4*>(&lrow[i]);
            acc = fmaf(a.x, w.x, acc); acc = fmaf(a.y, w.y, acc);
            acc = fmaf(a.z, w.z, acc); acc = fmaf(a.w, w.w, acc);
        }
#pragma unroll
        for (int o = 16; o > 0; o >>= 1) acc += __shfl_xor_sync(0xffffffffu, acc, o);
        if (lane == 0) {
            bf16* mp = reinterpret_cast<bf16*>(g_mid);
            size_t base = (size_t)row * (2 * R_) + 8 * (r >> 2) + (r & 3);
            bf16 h, l;
            split1(acc, h, l);
            mp[base] = h;
            mp[base + 4] = l;
        }
    }
}

__global__ __launch_bounds__(256) void rope_kernel(const int* __restrict__ positions)
{
    const int bs = blockIdx.x;
    const int b = bs / S_, s = bs % S_;
    __shared__ float cs[64], sn[64];
    if (threadIdx.x < 64) {
        float inv = powf(10000.f, -(float)threadIdx.x / 64.f);
        float f = (float)positions[s] * inv;
        cs[threadIdx.x] = cosf(f);
        sn[threadIdx.x] = sinf(f);
    }
    __syncthreads();
    float* base = g_qkv + (size_t)bs * O3_;
    bf16* qp = reinterpret_cast<bf16*>(g_q);
    bf16* kp = reinterpret_cast<bf16*>(g_k);
    for (int t = threadIdx.x; t < NH_ * 64; t += 256) {
        int h = t >> 6, i = t & 63;
        float c = cs[i], sv = sn[i];
        size_t row = (size_t)(b * NH_ + h) * S_ + s;
        size_t o1 = row * 256 + 8 * (i >> 2) + (i & 3);
        size_t o2 = row * 256 + 8 * ((64 + i) >> 2) + (i & 3);
        float x1 = base[h * HD_ + i], x2 = base[h * HD_ + 64 + i];
        bf16 h0, l0;
        split1(x1 * c - x2 * sv, h0, l0);  qp[o1] = h0; qp[o1 + 4] = l0;
        split1(x2 * c + x1 * sv, h0, l0);  qp[o2] = h0; qp[o2 + 4] = l0;
        float y1 = base[HID_ + h * HD_ + i], y2 = base[HID_ + h * HD_ + 64 + i];
        split1(y1 * c - y2 * sv, h0, l0);  kp[o1] = h0; kp[o1 + 4] = l0;
        split1(y2 * c + y1 * sv, h0, l0);  kp[o2] = h0; kp[o2 + 4] = l0;
    }
    __syncthreads();   // all q-region reads complete before overwrite below
    bf16* vp = reinterpret_cast<bf16*>(base);     // planar V into dead q-region
    for (int t = threadIdx.x; t < HID_; t += 256) {
        bf16 h0, l0;
        split1(base[2 * HID_ + t], h0, l0);
        vp[t] = h0;
        vp[HID_ + t] = l0;
    }
}

// causal softmax; grouped-split bf16 IN PLACE (PV's A)
__global__ __launch_bounds__(256) void softmax_kernel()
{
    const size_t row = blockIdx.x;
    const int q = (int)(row & (S_ - 1));
    float* p = g_scores + row * S_;
    const int tid = threadIdx.x;
    __shared__ float red[8];

    float4 v = *reinterpret_cast<const float4*>(p + tid * 4);
    const int e0 = tid * 4;

    float m = -1e30f;
    if (e0 + 0 <= q) m = fmaxf(m, v.x);
    if (e0 + 1 <= q) m = fmaxf(m, v.y);
    if (e0 + 2 <= q) m = fmaxf(m, v.z);
    if (e0 + 3 <= q) m = fmaxf(m, v.w);
#pragma unroll
    for (int o = 16; o > 0; o >>= 1) m = fmaxf(m, __shfl_xor_sync(0xffffffffu, m, o));
    if ((tid & 31) == 0) red[tid >> 5] = m;
    __syncthreads();
    float mm = red[0];
#pragma unroll
    for (int i = 1; i < 8; i++) mm = fmaxf(mm, red[i]);

    float4 e;
    e.x = (e0 + 0 <= q) ? __expf(v.x - mm) : 0.f;
    e.y = (e0 + 1 <= q) ? __expf(v.y - mm) : 0.f;
    e.z = (e0 + 2 <= q) ? __expf(v.z - mm) : 0.f;
    e.w = (e0 + 3 <= q) ? __expf(v.w - mm) : 0.f;
    float sum = e.x + e.y + e.z + e.w;
#pragma unroll
    for (int o = 16; o > 0; o >>= 1) sum += __shfl_xor_sync(0xffffffffu, sum, o);
    __syncthreads();
    if ((tid & 31) == 0) red[tid >> 5] = sum;
    __syncthreads();
    float tot = 0.f;
#pragma unroll
    for (int i = 0; i < 8; i++) tot += red[i];
    float inv = 1.f / tot;
    e.x *= inv; e.y *= inv; e.z *= inv; e.w *= inv;

    *reinterpret_cast<uint4*>(p + tid * 4) = split4pack(e);
}

// ---------------- launch ----------------
extern "C" void kernel_launch(void* const* d_in, const int* in_sizes, int n_in,
                              void* d_out, int out_size)
{
    const int*   positions = (const int*)d_in[0];
    const float* hs        = (const float*)d_in[1];
    const float* w_qkv     = (const float*)d_in[2];
    const float* w_dense   = (const float*)d_in[3];
    const float* lora_in   = (const float*)d_in[4];
    const float* lora_out  = (const float*)d_in[5];
    float* out = (float*)d_out;

    const size_t N_HS = (size_t)Bb_ * S_ * HID_;
    const size_t N_WQ = (size_t)O3_ * HID_;
    const size_t N_WD = (size_t)HID_ * HID_;

    cudaFuncSetAttribute(k_qkv,    cudaFuncAttributeMaxDynamicSharedMemorySize, SMEM_NT);
    cudaFuncSetAttribute(k_scores, cudaFuncAttributeMaxDynamicSharedMemorySize, SMEM_NT);
    cudaFuncSetAttribute(k_pv,     cudaFuncAttributeMaxDynamicSharedMemorySize, SMEM_PV);
    cudaFuncSetAttribute(k_dense,  cudaFuncAttributeMaxDynamicSharedMemorySize, SMEM_NT);

    split_hs_kernel<<<(unsigned)(N_HS / 1024), 256>>>(hs);
    split_wq_kernel<<<(unsigned)(N_WQ / 1024), 256>>>(w_qkv);

    lora_mid_kernel<<<Bb_ * S_, 256>>>(hs, lora_in);

    k_qkv<<<dim3(O3_ / 128, (Bb_ * S_) / 128), 256, SMEM_NT>>>(lora_out);

    rope_kernel<<<Bb_ * S_, 256>>>(positions);

    k_scores<<<dim3(36, Bb_ * NH_), 256, SMEM_NT>>>();

    split_wd_kernel<<<(unsigned)(N_WD / 1024), 256>>>(w_dense);

    softmax_kernel<<<Bb_ * NH_ * S_, 256>>>();

    k_pv<<<dim3(S_ / 128, Bb_ * NH_), 256, SMEM_PV>>>();

    k_dense<<<dim3(HID_ / 128, (Bb_ * S_) / 128), 256, SMEM_NT>>>(out);
}

// round 16
// speedup vs baseline: 1.6360x; 1.6360x over previous
#include <cuda_runtime.h>
#include <cuda_fp16.h>
#include <mma.h>
#include <math.h>
#include <stdint.h>
#include <type_traits>

using namespace nvcuda;

#define Bb_ 4
#define S_ 1024
#define HID_ 4096
#define NH_ 32
#define HD_ 128
#define O3_ 12288
#define R_ 32
#define SCALE_ 0.08838834764831845f

typedef __half hf;

// RULES (hard-won): device globals referenced ONLY inside kernel bodies.
// No tcgen05 (virtual arch compute_103 rejects 'a' features).
// 16B-multiple smem strides only. BK=16 load-then-compute schedule (BK=32 refuted 2x).

// ---- proven 6-symbol buffer set ----
__device__ float g_qkv[(size_t)Bb_ * S_ * O3_];        // fp32 qkv; q-region reused for planar V
__device__ float g_mid[Bb_ * S_ * R_];                 // grouped fp16 mid
__device__ float g_q[(size_t)Bb_ * NH_ * S_ * HD_];    // grouped fp16 q
__device__ float g_k[(size_t)Bb_ * NH_ * S_ * HD_];    // grouped k; later wd presplit
__device__ float g_scores[(size_t)Bb_ * NH_ * S_ * S_];// wq presplit -> scores -> grouped probs
__device__ float g_attn[(size_t)Bb_ * S_ * HID_];      // hs presplit -> fp32 attn

// Grouped-split layout (hf view): fp32 elem e -> hi at 8(e/4)+e%4, lo at +4.

__device__ __forceinline__ void split1(float x, hf& h, hf& l) {
    h = __float2half_rn(x);
    l = __float2half_rn(x - __half2float(h));
}
__device__ __forceinline__ void split4store(float4 v, hf* hp, hf* lp) {
    hf h0, h1, h2, h3, l0, l1, l2, l3;
    split1(v.x, h0, l0); split1(v.y, h1, l1);
    split1(v.z, h2, l2); split1(v.w, h3, l3);
    __half2 a, b, c, d;
    a.x = h0; a.y = h1; b.x = h2; b.y = h3;
    c.x = l0; c.y = l1; d.x = l2; d.y = l3;
    *reinterpret_cast<__half2*>(hp)     = a;
    *reinterpret_cast<__half2*>(hp + 2) = b;
    *reinterpret_cast<__half2*>(lp)     = c;
    *reinterpret_cast<__half2*>(lp + 2) = d;
}
__device__ __forceinline__ void split4hi(float4 v, hf* hp) {   // hi plane only
    hf h0, h1, h2, h3, l0, l1, l2, l3;
    split1(v.x, h0, l0); split1(v.y, h1, l1);
    split1(v.z, h2, l2); split1(v.w, h3, l3);
    __half2 a, b;
    a.x = h0; a.y = h1; b.x = h2; b.y = h3;
    *reinterpret_cast<__half2*>(hp)     = a;
    *reinterpret_cast<__half2*>(hp + 2) = b;
}
__device__ __forceinline__ uint4 split4pack(float4 v) {
    hf h0, h1, h2, h3, l0, l1, l2, l3;
    split1(v.x, h0, l0); split1(v.y, h1, l1);
    split1(v.z, h2, l2); split1(v.w, h3, l3);
    __half2 a, b, c, d;
    a.x = h0; a.y = h1; b.x = h2; b.y = h3;
    c.x = l0; c.y = l1; d.x = l2; d.y = l3;
    uint4 r;
    r.x = *reinterpret_cast<uint32_t*>(&a);
    r.y = *reinterpret_cast<uint32_t*>(&b);
    r.z = *reinterpret_cast<uint32_t*>(&c);
    r.w = *reinterpret_cast<uint32_t*>(&d);
    return r;
}

// ---------------- BK=16 pipelined wmma split GEMM core (R11/R14 skeleton) ----------------
// AMODE: 0 = fp32 rows (in-loop split), 1 = grouped-presplit hf rows
// BMODE: 1 = NT grouped-presplit, 3 = K-major planar presplit (Bv=H, Bv2=L)
// TERMS: 3 = AhBh+AhBl+AlBh ; 2 = AhBh+AlBh (B lo plane never touched)
template <int AMODE, int BMODE, int LORA, int SCALEOUT, int TERMS>
__device__ __forceinline__ void gemm_core(
    const void* __restrict__ Av, const int lda,
    const void* __restrict__ Bv, const void* __restrict__ Bv2, const int ldb,
    float* __restrict__ C, const int ldc,
    const int klim, const int bm, const int bn,
    const void* __restrict__ midv, const float* __restrict__ lorav)
{
    __shared__ __align__(16) hf smA[2][2][128][24];            // 24KB
    constexpr int BSTG = (BMODE == 3) ? (16 * 136) : (128 * 24);
    constexpr int BPL = (TERMS == 2) ? 1 : 2;                  // B planes staged
    __shared__ __align__(16) hf smB[2][BPL * BSTG];

    const int t = threadIdx.x;
    const int warp = t >> 5;
    const int wm = warp >> 2, wn = warp & 3;

    wmma::fragment<wmma::accumulator, 16, 16, 16, float> cfr[4][2];
#pragma unroll
    for (int mi = 0; mi < 4; mi++)
#pragma unroll
        for (int ni = 0; ni < 2; ni++) wmma::fill_fragment(cfr[mi][ni], 0.0f);

    const int kT = klim >> 4;
    const int total = kT + (LORA ? (R_ / 16) : 0);

    float4 fA[2], fB[2];
    uint4  uA[2], uB[2];
    uint2  uB2[2];

    auto loadT = [&](int tt) {
        const bool tail = LORA && (tt >= kT);
        const int k0 = tail ? ((tt - kT) << 4) : (tt << 4);
#pragma unroll
        for (int i = 0; i < 2; i++) {
            int idx = i * 256 + t;
            int row = idx >> 2, q4 = (idx & 3) * 4;
            // ---- A ----
            if (AMODE == 1) {
                const hf* src = tail
                    ? ((const hf*)midv + (size_t)(bm * 128 + row) * (2 * R_) + 2 * (k0 + q4))
                    : ((const hf*)Av + (size_t)(bm * 128 + row) * (2 * lda) + 2 * (k0 + q4));
                uA[i] = *reinterpret_cast<const uint4*>(src);
            } else {
                fA[i] = *reinterpret_cast<const float4*>(
                    (const float*)Av + (size_t)(bm * 128 + row) * lda + k0 + q4);
            }
            // ---- B ----
            if (BMODE == 1) {
                if (tail) {
                    fB[i] = *reinterpret_cast<const float4*>(
                        lorav + (size_t)(bn * 128 + row) * R_ + k0 + q4);
                } else {
                    const hf* src = (const hf*)Bv
                        + (size_t)(bn * 128 + row) * (2 * ldb) + 2 * (k0 + q4);
                    if (TERMS == 2) uB2[i] = *reinterpret_cast<const uint2*>(src);
                    else            uB[i]  = *reinterpret_cast<const uint4*>(src);
                }
            } else {  // BMODE == 3: K-major planar presplit
                int kr = idx >> 5, nc = (idx & 31) * 4;
                uint2 vh = *reinterpret_cast<const uint2*>(
                    (const hf*)Bv + (size_t)(k0 + kr) * ldb + nc);
                uint2 vl = *reinterpret_cast<const uint2*>(
                    (const hf*)Bv2 + (size_t)(k0 + kr) * ldb + nc);
                uB[i] = make_uint4(vh.x, vh.y, vl.x, vl.y);
            }
        }
    };

    auto storeT = [&](int st, int tt) {
        const bool tail = LORA && (tt >= kT);
#pragma unroll
        for (int i = 0; i < 2; i++) {
            int idx = i * 256 + t;
            int row = idx >> 2, q4 = (idx & 3) * 4;
            if (AMODE == 1) {
                *reinterpret_cast<uint2*>(&smA[st][0][row][q4]) = make_uint2(uA[i].x, uA[i].y);
                *reinterpret_cast<uint2*>(&smA[st][1][row][q4]) = make_uint2(uA[i].z, uA[i].w);
            } else {
                split4store(fA[i], &smA[st][0][row][q4], &smA[st][1][row][q4]);
            }
            if (BMODE == 1) {
                if (tail) {
                    if (TERMS == 2) split4hi(fB[i], &smB[st][row * 24 + q4]);
                    else split4store(fB[i], &smB[st][row * 24 + q4], &smB[st][BSTG + row * 24 + q4]);
                } else {
                    if (TERMS == 2) {
                        *reinterpret_cast<uint2*>(&smB[st][row * 24 + q4]) = uB2[i];
                    } else {
                        *reinterpret_cast<uint2*>(&smB[st][row * 24 + q4]) = make_uint2(uB[i].x, uB[i].y);
                        *reinterpret_cast<uint2*>(&smB[st][BSTG + row * 24 + q4]) = make_uint2(uB[i].z, uB[i].w);
                    }
                }
            } else {
                int kr = idx >> 5, nc = (idx & 31) * 4;
                *reinterpret_cast<uint2*>(&smB[st][kr * 136 + nc]) = make_uint2(uB[i].x, uB[i].y);
                *reinterpret_cast<uint2*>(&smB[st][BSTG + kr * 136 + nc]) = make_uint2(uB[i].z, uB[i].w);
            }
        }
    };

    loadT(0);
    storeT(0, 0);
    __syncthreads();

    using BLay = typename std::conditional<BMODE == 3, wmma::row_major, wmma::col_major>::type;

    for (int tt = 0; tt < total; tt++) {
        if (tt + 1 < total) loadT(tt + 1);
        const int st = tt & 1;

        wmma::fragment<wmma::matrix_b, 16, 16, 16, hf, BLay> bH[2], bL[2];
#pragma unroll
        for (int ni = 0; ni < 2; ni++) {
            if (BMODE == 3) {
                wmma::load_matrix_sync(bH[ni], &smB[st][wn * 32 + ni * 16], 136);
                wmma::load_matrix_sync(bL[ni], &smB[st][BSTG + wn * 32 + ni * 16], 136);
            } else {
                wmma::load_matrix_sync(bH[ni], &smB[st][(wn * 32 + ni * 16) * 24], 24);
                if (TERMS == 3)
                    wmma::load_matrix_sync(bL[ni], &smB[st][BSTG + (wn * 32 + ni * 16) * 24], 24);
            }
        }
#pragma unroll
        for (int mi = 0; mi < 4; mi++) {
            wmma::fragment<wmma::matrix_a, 16, 16, 16, hf, wmma::row_major> aH, aL;
            wmma::load_matrix_sync(aH, &smA[st][0][wm * 64 + mi * 16][0], 24);
            wmma::load_matrix_sync(aL, &smA[st][1][wm * 64 + mi * 16][0], 24);
#pragma unroll
            for (int ni = 0; ni < 2; ni++) {
                wmma::mma_sync(cfr[mi][ni], aH, bH[ni], cfr[mi][ni]);
                if (TERMS == 3)
                    wmma::mma_sync(cfr[mi][ni], aH, bL[ni], cfr[mi][ni]);
                wmma::mma_sync(cfr[mi][ni], aL, bH[ni], cfr[mi][ni]);
            }
        }
        if (tt + 1 < total) storeT((tt + 1) & 1, tt + 1);
        __syncthreads();
    }

#pragma unroll
    for (int mi = 0; mi < 4; mi++)
#pragma unroll
        for (int ni = 0; ni < 2; ni++) {
            if (SCALEOUT) {
#pragma unroll
                for (int e = 0; e < cfr[mi][ni].num_elements; e++) cfr[mi][ni].x[e] *= SCALE_;
            }
            wmma::store_matrix_sync(
                C + (size_t)(bm * 128 + wm * 64 + mi * 16) * ldc + bn * 128 + wn * 32 + ni * 16,
                cfr[mi][ni], ldc, wmma::mem_row_major);
        }
}

// ---------------- GEMM wrapper kernels ----------------
__global__ __launch_bounds__(256, 2) void k_qkv(const float* __restrict__ lora_out)
{
    const int b = (int)(blockIdx.y >> 3);
    gemm_core<1, 1, 1, 0, 2>(g_attn, HID_, g_scores, nullptr, HID_, g_qkv, O3_, HID_,
                             blockIdx.y, blockIdx.x,
                             g_mid, lora_out + (size_t)b * O3_ * R_);
}

__global__ __launch_bounds__(256, 2) void k_scores()
{
    const int ti = (int)blockIdx.x;                // lower-triangle tile index [0,36)
    int bm = (int)((sqrtf(8.f * ti + 1.f) - 1.f) * 0.5f);
    while ((bm + 1) * (bm + 2) / 2 <= ti) ++bm;
    while (bm * (bm + 1) / 2 > ti) --bm;
    const int bn = ti - bm * (bm + 1) / 2;
    const size_t z = blockIdx.y;
    gemm_core<1, 1, 0, 1, 3>(g_q + z * S_ * HD_, HD_, g_k + z * S_ * HD_, nullptr, HD_,
                             g_scores + z * S_ * S_, S_, HD_,
                             bm, bn, nullptr, nullptr);
}

__global__ __launch_bounds__(256, 2) void k_pv()
{
    const size_t z = blockIdx.y;
    const int b = (int)(z >> 5), h = (int)(z & 31);
    const int bm = (int)blockIdx.x;
    const int klim = (bm + 1) * 128;
    const hf* vbase = reinterpret_cast<const hf*>(g_qkv + (size_t)b * S_ * O3_);
    gemm_core<1, 3, 0, 0, 3>(g_scores + z * S_ * S_, S_,
                             vbase + h * HD_, vbase + HID_ + h * HD_, 2 * O3_,
                             g_attn + (size_t)b * S_ * HID_ + h * HD_, HID_,
                             klim, bm, 0, nullptr, nullptr);
}

__global__ __launch_bounds__(256, 2) void k_dense(float* __restrict__ out)
{
    gemm_core<0, 1, 0, 0, 2>(g_attn, HID_, g_k, nullptr, HID_, out, HID_, HID_,
                             blockIdx.y, blockIdx.x, nullptr, nullptr);
}

// ---------------- split kernels (dst globals INSIDE) ----------------
__global__ __launch_bounds__(256) void split_hs_kernel(const float* __restrict__ s)
{
    size_t e = ((size_t)blockIdx.x * 256 + threadIdx.x) * 4;
    float4 v = *reinterpret_cast<const float4*>(s + e);
    *reinterpret_cast<uint4*>(reinterpret_cast<hf*>(g_attn) + 2 * e) = split4pack(v);
}
__global__ __launch_bounds__(256) void split_wq_kernel(const float* __restrict__ s)
{
    size_t e = ((size_t)blockIdx.x * 256 + threadIdx.x) * 4;
    float4 v = *reinterpret_cast<const float4*>(s + e);
    *reinterpret_cast<uint4*>(reinterpret_cast<hf*>(g_scores) + 2 * e) = split4pack(v);
}
__global__ __launch_bounds__(256) void split_wd_kernel(const float* __restrict__ s)
{
    size_t e = ((size_t)blockIdx.x * 256 + threadIdx.x) * 4;
    float4 v = *reinterpret_cast<const float4*>(s + e);
    *reinterpret_cast<uint4*>(reinterpret_cast<hf*>(g_k) + 2 * e) = split4pack(v);
}

// ---------------- small kernels ----------------
__global__ __launch_bounds__(256) void lora_mid_kernel(
    const float* __restrict__ hs, const float* __restrict__ lin)
{
    const int row = blockIdx.x;
    const int b = row / S_;
    __shared__ float sh[HID_];
    for (int i = threadIdx.x; i < HID_; i += 256) sh[i] = hs[(size_t)row * HID_ + i];
    __syncthreads();
    const int warp = threadIdx.x >> 5, lane = threadIdx.x & 31;
    for (int r = warp; r < R_; r += 8) {
        const float* lrow = lin + ((size_t)b * R_ + r) * HID_;
        float acc = 0.f;
        for (int i = lane * 4; i < HID_; i += 128) {
            float4 a = *reinterpret_cast<const float4*>(&sh[i]);
            float4 w = *reinterpret_cast<const float4*>(&lrow[i]);
            acc = fmaf(a.x, w.x, acc); acc = fmaf(a.y, w.y, acc);
            acc = fmaf(a.z, w.z, acc); acc = fmaf(a.w, w.w, acc);
        }
#pragma unroll
        for (int o = 16; o > 0; o >>= 1) acc += __shfl_xor_sync(0xffffffffu, acc, o);
        if (lane == 0) {
            hf* mp = reinterpret_cast<hf*>(g_mid);
            size_t base = (size_t)row * (2 * R_) + 8 * (r >> 2) + (r & 3);
            hf h, l;
            split1(acc, h, l);
            mp[base] = h;
            mp[base + 4] = l;
        }
    }
}

__global__ __launch_bounds__(256) void rope_kernel(const int* __restrict__ positions)
{
    const int bs = blockIdx.x;
    const int b = bs / S_, s = bs % S_;
    __shared__ float cs[64], sn[64];
    if (threadIdx.x < 64) {
        float inv = powf(10000.f, -(float)threadIdx.x / 64.f);
        float f = (float)positions[s] * inv;
        cs[threadIdx.x] = cosf(f);
        sn[threadIdx.x] = sinf(f);
    }
    __syncthreads();
    float* base = g_qkv + (size_t)bs * O3_;
    hf* qp = reinterpret_cast<hf*>(g_q);
    hf* kp = reinterpret_cast<hf*>(g_k);
    for (int t = threadIdx.x; t < NH_ * 64; t += 256) {
        int h = t >> 6, i = t & 63;
        float c = cs[i], sv = sn[i];
        size_t row = (size_t)(b * NH_ + h) * S_ + s;
        size_t o1 = row * 256 + 8 * (i >> 2) + (i & 3);
        size_t o2 = row * 256 + 8 * ((64 + i) >> 2) + (i & 3);
        float x1 = base[h * HD_ + i], x2 = base[h * HD_ + 64 + i];
        hf h0, l0;
        split1(x1 * c - x2 * sv, h0, l0);  qp[o1] = h0; qp[o1 + 4] = l0;
        split1(x2 * c + x1 * sv, h0, l0);  qp[o2] = h0; qp[o2 + 4] = l0;
        float y1 = base[HID_ + h * HD_ + i], y2 = base[HID_ + h * HD_ + 64 + i];
        split1(y1 * c - y2 * sv, h0, l0);  kp[o1] = h0; kp[o1 + 4] = l0;
        split1(y2 * c + y1 * sv, h0, l0);  kp[o2] = h0; kp[o2 + 4] = l0;
    }
    __syncthreads();   // all q-region reads complete before overwrite below
    hf* vp = reinterpret_cast<hf*>(base);     // planar V into dead q-region
    for (int t = threadIdx.x; t < HID_; t += 256) {
        hf h0, l0;
        split1(base[2 * HID_ + t], h0, l0);
        vp[t] = h0;
        vp[HID_ + t] = l0;
    }
}

// causal softmax; grouped-split fp16 IN PLACE (PV's A)
__global__ __launch_bounds__(256) void softmax_kernel()
{
    const size_t row = blockIdx.x;
    const int q = (int)(row & (S_ - 1));
    float* p = g_scores + row * S_;
    const int tid = threadIdx.x;
    __shared__ float red[8];

    float4 v = *reinterpret_cast<const float4*>(p + tid * 4);
    const int e0 = tid * 4;

    float m = -1e30f;
    if (e0 + 0 <= q) m = fmaxf(m, v.x);
    if (e0 + 1 <= q) m = fmaxf(m, v.y);
    if (e0 + 2 <= q) m = fmaxf(m, v.z);
    if (e0 + 3 <= q) m = fmaxf(m, v.w);
#pragma unroll
    for (int o = 16; o > 0; o >>= 1) m = fmaxf(m, __shfl_xor_sync(0xffffffffu, m, o));
    if ((tid & 31) == 0) red[tid >> 5] = m;
    __syncthreads();
    float mm = red[0];
#pragma unroll
    for (int i = 1; i < 8; i++) mm = fmaxf(mm, red[i]);

    float4 e;
    e.x = (e0 + 0 <= q) ? __expf(v.x - mm) : 0.f;
    e.y = (e0 + 1 <= q) ? __expf(v.y - mm) : 0.f;
    e.z = (e0 + 2 <= q) ? __expf(v.z - mm) : 0.f;
    e.w = (e0 + 3 <= q) ? __expf(v.w - mm) : 0.f;
    float sum = e.x + e.y + e.z + e.w;
#pragma unroll
    for (int o = 16; o > 0; o >>= 1) sum += __shfl_xor_sync(0xffffffffu, sum, o);
    __syncthreads();
    if ((tid & 31) == 0) red[tid >> 5] = sum;
    __syncthreads();
    float tot = 0.f;
#pragma unroll
    for (int i = 0; i < 8; i++) tot += red[i];
    float inv = 1.f / tot;
    e.x *= inv; e.y *= inv; e.z *= inv; e.w *= inv;

    *reinterpret_cast<uint4*>(p + tid * 4) = split4pack(e);
}

// ---------------- launch ----------------
extern "C" void kernel_launch(void* const* d_in, const int* in_sizes, int n_in,
                              void* d_out, int out_size)
{
    const int*   positions = (const int*)d_in[0];
    const float* hs        = (const float*)d_in[1];
    const float* w_qkv     = (const float*)d_in[2];
    const float* w_dense   = (const float*)d_in[3];
    const float* lora_in   = (const float*)d_in[4];
    const float* lora_out  = (const float*)d_in[5];
    float* out = (float*)d_out;

    const size_t N_HS = (size_t)Bb_ * S_ * HID_;
    const size_t N_WQ = (size_t)O3_ * HID_;
    const size_t N_WD = (size_t)HID_ * HID_;

    split_hs_kernel<<<(unsigned)(N_HS / 1024), 256>>>(hs);
    split_wq_kernel<<<(unsigned)(N_WQ / 1024), 256>>>(w_qkv);

    lora_mid_kernel<<<Bb_ * S_, 256>>>(hs, lora_in);

    k_qkv<<<dim3(O3_ / 128, (Bb_ * S_) / 128), 256>>>(lora_out);

    rope_kernel<<<Bb_ * S_, 256>>>(positions);

    k_scores<<<dim3(36, Bb_ * NH_), 256>>>();

    // g_k dead after k_scores: stash wd presplit there for k_dense
    split_wd_kernel<<<(unsigned)(N_WD / 1024), 256>>>(w_dense);

    softmax_kernel<<<Bb_ * NH_ * S_, 256>>>();

    k_pv<<<dim3(S_ / 128, Bb_ * NH_), 256>>>();

    k_dense<<<dim3(HID_ / 128, (Bb_ * S_) / 128), 256>>>(out);
}

// round 17
// speedup vs baseline: 1.6517x; 1.0096x over previous
#include <cuda_runtime.h>
#include <cuda_fp16.h>
#include <mma.h>
#include <math.h>
#include <stdint.h>
#include <type_traits>

using namespace nvcuda;

#define Bb_ 4
#define S_ 1024
#define HID_ 4096
#define NH_ 32
#define HD_ 128
#define O3_ 12288
#define R_ 32
#define SCALE_ 0.08838834764831845f

typedef __half hf;

// RULES (hard-won): device globals referenced ONLY inside kernel bodies.
// No tcgen05 (virtual arch compute_103 rejects 'a' features).
// 16B-multiple smem strides only. BK=16 load-then-compute schedule (BK=32 refuted 2x).

// ---- proven 6-symbol buffer set ----
__device__ float g_qkv[(size_t)Bb_ * S_ * O3_];        // fp32 qkv; q-region reused for planar V
__device__ float g_mid[Bb_ * S_ * R_];                 // grouped fp16 mid
__device__ float g_q[(size_t)Bb_ * NH_ * S_ * HD_];    // grouped fp16 q
__device__ float g_k[(size_t)Bb_ * NH_ * S_ * HD_];    // grouped k; later wd presplit
__device__ float g_scores[(size_t)Bb_ * NH_ * S_ * S_];// wq presplit -> scores -> grouped probs
__device__ float g_attn[(size_t)Bb_ * S_ * HID_];      // grouped hs -> grouped attn

// Grouped-split layout (hf view): fp32 elem e -> hi at 8(e/4)+e%4, lo at +4.

__device__ __forceinline__ void split1(float x, hf& h, hf& l) {
    h = __float2half_rn(x);
    l = __float2half_rn(x - __half2float(h));
}
__device__ __forceinline__ void split4store(float4 v, hf* hp, hf* lp) {
    hf h0, h1, h2, h3, l0, l1, l2, l3;
    split1(v.x, h0, l0); split1(v.y, h1, l1);
    split1(v.z, h2, l2); split1(v.w, h3, l3);
    __half2 a, b, c, d;
    a.x = h0; a.y = h1; b.x = h2; b.y = h3;
    c.x = l0; c.y = l1; d.x = l2; d.y = l3;
    *reinterpret_cast<__half2*>(hp)     = a;
    *reinterpret_cast<__half2*>(hp + 2) = b;
    *reinterpret_cast<__half2*>(lp)     = c;
    *reinterpret_cast<__half2*>(lp + 2) = d;
}
__device__ __forceinline__ void split4hi(float4 v, hf* hp) {
    hf h0, h1, h2, h3, l0, l1, l2, l3;
    split1(v.x, h0, l0); split1(v.y, h1, l1);
    split1(v.z, h2, l2); split1(v.w, h3, l3);
    __half2 a, b;
    a.x = h0; a.y = h1; b.x = h2; b.y = h3;
    *reinterpret_cast<__half2*>(hp)     = a;
    *reinterpret_cast<__half2*>(hp + 2) = b;
}
__device__ __forceinline__ uint4 split4pack(float4 v) {
    hf h0, h1, h2, h3, l0, l1, l2, l3;
    split1(v.x, h0, l0); split1(v.y, h1, l1);
    split1(v.z, h2, l2); split1(v.w, h3, l3);
    __half2 a, b, c, d;
    a.x = h0; a.y = h1; b.x = h2; b.y = h3;
    c.x = l0; c.y = l1; d.x = l2; d.y = l3;
    uint4 r;
    r.x = *reinterpret_cast<uint32_t*>(&a);
    r.y = *reinterpret_cast<uint32_t*>(&b);
    r.z = *reinterpret_cast<uint32_t*>(&c);
    r.w = *reinterpret_cast<uint32_t*>(&d);
    return r;
}

// ---------------- BK=16 pipelined wmma split GEMM core ----------------
// AMODE: 0 = fp32 rows (in-loop split), 1 = grouped-presplit hf rows
// BMODE: 1 = NT grouped-presplit, 3 = K-major planar presplit (Bv=H, Bv2=L)
// TERMS: 3 = AhBh+AhBl+AlBh ; 2 = AhBh+AlBh (B lo plane never touched)
// SPLITW: 1 = write grouped-split hf output (C reinterpreted as hf*), else fp32.
template <int AMODE, int BMODE, int LORA, int SCALEOUT, int TERMS, int SPLITW>
__device__ __forceinline__ void gemm_core(
    const void* __restrict__ Av, const int lda,
    const void* __restrict__ Bv, const void* __restrict__ Bv2, const int ldb,
    float* __restrict__ C, const int ldc,
    const int klim, const int bm, const int bn,
    const void* __restrict__ midv, const float* __restrict__ lorav)
{
    __shared__ __align__(16) hf smA[2][2][128][24];            // 24KB
    constexpr int BSTG = (BMODE == 3) ? (16 * 136) : (128 * 24);
    constexpr int BPL = (TERMS == 2) ? 1 : 2;
    __shared__ __align__(16) hf smB[2][BPL * BSTG];

    const int t = threadIdx.x;
    const int warp = t >> 5;
    const int wm = warp >> 2, wn = warp & 3;
    const int lane = t & 31;

    wmma::fragment<wmma::accumulator, 16, 16, 16, float> cfr[4][2];
#pragma unroll
    for (int mi = 0; mi < 4; mi++)
#pragma unroll
        for (int ni = 0; ni < 2; ni++) wmma::fill_fragment(cfr[mi][ni], 0.0f);

    const int kT = klim >> 4;
    const int total = kT + (LORA ? (R_ / 16) : 0);

    float4 fA[2], fB[2];
    uint4  uA[2], uB[2];
    uint2  uB2[2];

    auto loadT = [&](int tt) {
        const bool tail = LORA && (tt >= kT);
        const int k0 = tail ? ((tt - kT) << 4) : (tt << 4);
#pragma unroll
        for (int i = 0; i < 2; i++) {
            int idx = i * 256 + t;
            int row = idx >> 2, q4 = (idx & 3) * 4;
            // ---- A ----
            if (AMODE == 1) {
                const hf* src = tail
                    ? ((const hf*)midv + (size_t)(bm * 128 + row) * (2 * R_) + 2 * (k0 + q4))
                    : ((const hf*)Av + (size_t)(bm * 128 + row) * (2 * lda) + 2 * (k0 + q4));
                uA[i] = *reinterpret_cast<const uint4*>(src);
            } else {
                fA[i] = *reinterpret_cast<const float4*>(
                    (const float*)Av + (size_t)(bm * 128 + row) * lda + k0 + q4);
            }
            // ---- B ----
            if (BMODE == 1) {
                if (tail) {
                    fB[i] = *reinterpret_cast<const float4*>(
                        lorav + (size_t)(bn * 128 + row) * R_ + k0 + q4);
                } else {
                    const hf* src = (const hf*)Bv
                        + (size_t)(bn * 128 + row) * (2 * ldb) + 2 * (k0 + q4);
                    if (TERMS == 2) uB2[i] = *reinterpret_cast<const uint2*>(src);
                    else            uB[i]  = *reinterpret_cast<const uint4*>(src);
                }
            } else {  // BMODE == 3: K-major planar presplit
                int kr = idx >> 5, nc = (idx & 31) * 4;
                uint2 vh = *reinterpret_cast<const uint2*>(
                    (const hf*)Bv + (size_t)(k0 + kr) * ldb + nc);
                if (TERMS == 2) {
                    uB2[i] = vh;
                } else {
                    uint2 vl = *reinterpret_cast<const uint2*>(
                        (const hf*)Bv2 + (size_t)(k0 + kr) * ldb + nc);
                    uB[i] = make_uint4(vh.x, vh.y, vl.x, vl.y);
                }
            }
        }
    };

    auto storeT = [&](int st, int tt) {
        const bool tail = LORA && (tt >= kT);
#pragma unroll
        for (int i = 0; i < 2; i++) {
            int idx = i * 256 + t;
            int row = idx >> 2, q4 = (idx & 3) * 4;
            if (AMODE == 1) {
                *reinterpret_cast<uint2*>(&smA[st][0][row][q4]) = make_uint2(uA[i].x, uA[i].y);
                *reinterpret_cast<uint2*>(&smA[st][1][row][q4]) = make_uint2(uA[i].z, uA[i].w);
            } else {
                split4store(fA[i], &smA[st][0][row][q4], &smA[st][1][row][q4]);
            }
            if (BMODE == 1) {
                if (tail) {
                    if (TERMS == 2) split4hi(fB[i], &smB[st][row * 24 + q4]);
                    else split4store(fB[i], &smB[st][row * 24 + q4], &smB[st][BSTG + row * 24 + q4]);
                } else {
                    if (TERMS == 2) {
                        *reinterpret_cast<uint2*>(&smB[st][row * 24 + q4]) = uB2[i];
                    } else {
                        *reinterpret_cast<uint2*>(&smB[st][row * 24 + q4]) = make_uint2(uB[i].x, uB[i].y);
                        *reinterpret_cast<uint2*>(&smB[st][BSTG + row * 24 + q4]) = make_uint2(uB[i].z, uB[i].w);
                    }
                }
            } else {
                int kr = idx >> 5, nc = (idx & 31) * 4;
                if (TERMS == 2) {
                    *reinterpret_cast<uint2*>(&smB[st][kr * 136 + nc]) = uB2[i];
                } else {
                    *reinterpret_cast<uint2*>(&smB[st][kr * 136 + nc]) = make_uint2(uB[i].x, uB[i].y);
                    *reinterpret_cast<uint2*>(&smB[st][BSTG + kr * 136 + nc]) = make_uint2(uB[i].z, uB[i].w);
                }
            }
        }
    };

    loadT(0);
    storeT(0, 0);
    __syncthreads();

    using BLay = typename std::conditional<BMODE == 3, wmma::row_major, wmma::col_major>::type;

    for (int tt = 0; tt < total; tt++) {
        if (tt + 1 < total) loadT(tt + 1);
        const int st = tt & 1;

        wmma::fragment<wmma::matrix_b, 16, 16, 16, hf, BLay> bH[2], bL[2];
#pragma unroll
        for (int ni = 0; ni < 2; ni++) {
            if (BMODE == 3) {
                wmma::load_matrix_sync(bH[ni], &smB[st][wn * 32 + ni * 16], 136);
                if (TERMS == 3)
                    wmma::load_matrix_sync(bL[ni], &smB[st][BSTG + wn * 32 + ni * 16], 136);
            } else {
                wmma::load_matrix_sync(bH[ni], &smB[st][(wn * 32 + ni * 16) * 24], 24);
                if (TERMS == 3)
                    wmma::load_matrix_sync(bL[ni], &smB[st][BSTG + (wn * 32 + ni * 16) * 24], 24);
            }
        }
#pragma unroll
        for (int mi = 0; mi < 4; mi++) {
            wmma::fragment<wmma::matrix_a, 16, 16, 16, hf, wmma::row_major> aH, aL;
            wmma::load_matrix_sync(aH, &smA[st][0][wm * 64 + mi * 16][0], 24);
            wmma::load_matrix_sync(aL, &smA[st][1][wm * 64 + mi * 16][0], 24);
#pragma unroll
            for (int ni = 0; ni < 2; ni++) {
                wmma::mma_sync(cfr[mi][ni], aH, bH[ni], cfr[mi][ni]);
                if (TERMS == 3)
                    wmma::mma_sync(cfr[mi][ni], aH, bL[ni], cfr[mi][ni]);
                wmma::mma_sync(cfr[mi][ni], aL, bH[ni], cfr[mi][ni]);
            }
        }
        if (tt + 1 < total) storeT((tt + 1) & 1, tt + 1);
        __syncthreads();
    }

    if (SPLITW) {
        // stage fp32 through smem (stride 24 = 16B mult), split once, write grouped hf
        float* stg = reinterpret_cast<float*>(&smA[0][0][0][0]) + warp * 384;  // 16*24
        hf* OH = reinterpret_cast<hf*>(C);
        const int r = lane & 15, hsel = lane >> 4;
#pragma unroll
        for (int mi = 0; mi < 4; mi++)
#pragma unroll
            for (int ni = 0; ni < 2; ni++) {
                wmma::store_matrix_sync(stg, cfr[mi][ni], 24, wmma::mem_row_major);
                __syncwarp();
                float4 v0 = *reinterpret_cast<const float4*>(stg + r * 24 + hsel * 8);
                float4 v1 = *reinterpret_cast<const float4*>(stg + r * 24 + hsel * 8 + 4);
                size_t row = (size_t)(bm * 128 + wm * 64 + mi * 16 + r);
                int colL = wn * 32 + ni * 16 + hsel * 8;
                hf* dst = OH + row * (size_t)(2 * ldc) + 2 * colL;
                *reinterpret_cast<uint4*>(dst)     = split4pack(v0);
                *reinterpret_cast<uint4*>(dst + 8) = split4pack(v1);
                __syncwarp();
            }
        return;
    }

#pragma unroll
    for (int mi = 0; mi < 4; mi++)
#pragma unroll
        for (int ni = 0; ni < 2; ni++) {
            if (SCALEOUT) {
#pragma unroll
                for (int e = 0; e < cfr[mi][ni].num_elements; e++) cfr[mi][ni].x[e] *= SCALE_;
            }
            wmma::store_matrix_sync(
                C + (size_t)(bm * 128 + wm * 64 + mi * 16) * ldc + bn * 128 + wn * 32 + ni * 16,
                cfr[mi][ni], ldc, wmma::mem_row_major);
        }
}

// ---------------- GEMM wrapper kernels ----------------
__global__ __launch_bounds__(256, 2) void k_qkv(const float* __restrict__ lora_out)
{
    const int b = (int)(blockIdx.y >> 3);
    gemm_core<1, 1, 1, 0, 2, 0>(g_attn, HID_, g_scores, nullptr, HID_, g_qkv, O3_, HID_,
                                blockIdx.y, blockIdx.x,
                                g_mid, lora_out + (size_t)b * O3_ * R_);
}

__global__ __launch_bounds__(256, 2) void k_scores()
{
    const int ti = (int)blockIdx.x;                // lower-triangle tile index [0,36)
    int bm = (int)((sqrtf(8.f * ti + 1.f) - 1.f) * 0.5f);
    while ((bm + 1) * (bm + 2) / 2 <= ti) ++bm;
    while (bm * (bm + 1) / 2 > ti) --bm;
    const int bn = ti - bm * (bm + 1) / 2;
    const size_t z = blockIdx.y;
    gemm_core<1, 1, 0, 1, 3, 0>(g_q + z * S_ * HD_, HD_, g_k + z * S_ * HD_, nullptr, HD_,
                                g_scores + z * S_ * S_, S_, HD_,
                                bm, bn, nullptr, nullptr);
}

__global__ __launch_bounds__(256, 2) void k_pv()
{
    const size_t z = blockIdx.y;
    const int b = (int)(z >> 5), h = (int)(z & 31);
    const int bm = (int)blockIdx.x;
    const int klim = (bm + 1) * 128;
    const hf* vbase = reinterpret_cast<const hf*>(g_qkv + (size_t)b * S_ * O3_);
    // grouped attn output base, pre-offset to this head's columns
    hf* OH = reinterpret_cast<hf*>(g_attn) + ((size_t)b * S_ * HID_) * 2 + (size_t)h * HD_ * 2;
    gemm_core<1, 3, 0, 0, 2, 1>(g_scores + z * S_ * S_, S_,
                                vbase + h * HD_, nullptr, 2 * O3_,
                                reinterpret_cast<float*>(OH), HID_,
                                klim, bm, 0, nullptr, nullptr);
}

__global__ __launch_bounds__(256, 2) void k_dense(float* __restrict__ out)
{
    gemm_core<1, 1, 0, 0, 2, 0>(g_attn, HID_, g_k, nullptr, HID_, out, HID_, HID_,
                                blockIdx.y, blockIdx.x, nullptr, nullptr);
}

// ---------------- split kernels (dst globals INSIDE) ----------------
__global__ __launch_bounds__(256) void split_hs_kernel(const float* __restrict__ s)
{
    size_t e = ((size_t)blockIdx.x * 256 + threadIdx.x) * 4;
    float4 v = *reinterpret_cast<const float4*>(s + e);
    *reinterpret_cast<uint4*>(reinterpret_cast<hf*>(g_attn) + 2 * e) = split4pack(v);
}
__global__ __launch_bounds__(256) void split_wq_kernel(const float* __restrict__ s)
{
    size_t e = ((size_t)blockIdx.x * 256 + threadIdx.x) * 4;
    float4 v = *reinterpret_cast<const float4*>(s + e);
    *reinterpret_cast<uint4*>(reinterpret_cast<hf*>(g_scores) + 2 * e) = split4pack(v);
}
__global__ __launch_bounds__(256) void split_wd_kernel(const float* __restrict__ s)
{
    size_t e = ((size_t)blockIdx.x * 256 + threadIdx.x) * 4;
    float4 v = *reinterpret_cast<const float4*>(s + e);
    *reinterpret_cast<uint4*>(reinterpret_cast<hf*>(g_k) + 2 * e) = split4pack(v);
}

// ---------------- small kernels ----------------
__global__ __launch_bounds__(256) void lora_mid_kernel(
    const float* __restrict__ hs, const float* __restrict__ lin)
{
    const int row = blockIdx.x;
    const int b = row / S_;
    __shared__ float sh[HID_];
    for (int i = threadIdx.x; i < HID_; i += 256) sh[i] = hs[(size_t)row * HID_ + i];
    __syncthreads();
    const int warp = threadIdx.x >> 5, lane = threadIdx.x & 31;
    for (int r = warp; r < R_; r += 8) {
        const float* lrow = lin + ((size_t)b * R_ + r) * HID_;
        float acc = 0.f;
        for (int i = lane * 4; i < HID_; i += 128) {
            float4 a = *reinterpret_cast<const float4*>(&sh[i]);
            float4 w = *reinterpret_cast<const float4*>(&lrow[i]);
            acc = fmaf(a.x, w.x, acc); acc = fmaf(a.y, w.y, acc);
            acc = fmaf(a.z, w.z, acc); acc = fmaf(a.w, w.w, acc);
        }
#pragma unroll
        for (int o = 16; o > 0; o >>= 1) acc += __shfl_xor_sync(0xffffffffu, acc, o);
        if (lane == 0) {
            hf* mp = reinterpret_cast<hf*>(g_mid);
            size_t base = (size_t)row * (2 * R_) + 8 * (r >> 2) + (r & 3);
            hf h, l;
            split1(acc, h, l);
            mp[base] = h;
            mp[base + 4] = l;
        }
    }
}

__global__ __launch_bounds__(256) void rope_kernel(const int* __restrict__ positions)
{
    const int bs = blockIdx.x;
    const int b = bs / S_, s = bs % S_;
    __shared__ float cs[64], sn[64];
    if (threadIdx.x < 64) {
        float inv = powf(10000.f, -(float)threadIdx.x / 64.f);
        float f = (float)positions[s] * inv;
        cs[threadIdx.x] = cosf(f);
        sn[threadIdx.x] = sinf(f);
    }
    __syncthreads();
    float* base = g_qkv + (size_t)bs * O3_;
    hf* qp = reinterpret_cast<hf*>(g_q);
    hf* kp = reinterpret_cast<hf*>(g_k);
    for (int t = threadIdx.x; t < NH_ * 64; t += 256) {
        int h = t >> 6, i = t & 63;
        float c = cs[i], sv = sn[i];
        size_t row = (size_t)(b * NH_ + h) * S_ + s;
        size_t o1 = row * 256 + 8 * (i >> 2) + (i & 3);
        size_t o2 = row * 256 + 8 * ((64 + i) >> 2) + (i & 3);
        float x1 = base[h * HD_ + i], x2 = base[h * HD_ + 64 + i];
        hf h0, l0;
        split1(x1 * c - x2 * sv, h0, l0);  qp[o1] = h0; qp[o1 + 4] = l0;
        split1(x2 * c + x1 * sv, h0, l0);  qp[o2] = h0; qp[o2 + 4] = l0;
        float y1 = base[HID_ + h * HD_ + i], y2 = base[HID_ + h * HD_ + 64 + i];
        split1(y1 * c - y2 * sv, h0, l0);  kp[o1] = h0; kp[o1 + 4] = l0;
        split1(y2 * c + y1 * sv, h0, l0);  kp[o2] = h0; kp[o2 + 4] = l0;
    }
    __syncthreads();   // all q-region reads complete before overwrite below
    hf* vp = reinterpret_cast<hf*>(base);     // planar V into dead q-region
    for (int t = threadIdx.x; t < HID_; t += 256) {
        hf h0, l0;
        split1(base[2 * HID_ + t], h0, l0);
        vp[t] = h0;
        vp[HID_ + t] = l0;
    }
}

// causal softmax; grouped-split fp16 IN PLACE (PV's A)
__global__ __launch_bounds__(256) void softmax_kernel()
{
    const size_t row = blockIdx.x;
    const int q = (int)(row & (S_ - 1));
    float* p = g_scores + row * S_;
    const int tid = threadIdx.x;
    __shared__ float red[8];

    float4 v = *reinterpret_cast<const float4*>(p + tid * 4);
    const int e0 = tid * 4;

    float m = -1e30f;
    if (e0 + 0 <= q) m = fmaxf(m, v.x);
    if (e0 + 1 <= q) m = fmaxf(m, v.y);
    if (e0 + 2 <= q) m = fmaxf(m, v.z);
    if (e0 + 3 <= q) m = fmaxf(m, v.w);
#pragma unroll
    for (int o = 16; o > 0; o >>= 1) m = fmaxf(m, __shfl_xor_sync(0xffffffffu, m, o));
    if ((tid & 31) == 0) red[tid >> 5] = m;
    __syncthreads();
    float mm = red[0];
#pragma unroll
    for (int i = 1; i < 8; i++) mm = fmaxf(mm, red[i]);

    float4 e;
    e.x = (e0 + 0 <= q) ? __expf(v.x - mm) : 0.f;
    e.y = (e0 + 1 <= q) ? __expf(v.y - mm) : 0.f;
    e.z = (e0 + 2 <= q) ? __expf(v.z - mm) : 0.f;
    e.w = (e0 + 3 <= q) ? __expf(v.w - mm) : 0.f;
    float sum = e.x + e.y + e.z + e.w;
#pragma unroll
    for (int o = 16; o > 0; o >>= 1) sum += __shfl_xor_sync(0xffffffffu, sum, o);
    __syncthreads();
    if ((tid & 31) == 0) red[tid >> 5] = sum;
    __syncthreads();
    float tot = 0.f;
#pragma unroll
    for (int i = 0; i < 8; i++) tot += red[i];
    float inv = 1.f / tot;
    e.x *= inv; e.y *= inv; e.z *= inv; e.w *= inv;

    *reinterpret_cast<uint4*>(p + tid * 4) = split4pack(e);
}

// ---------------- launch ----------------
extern "C" void kernel_launch(void* const* d_in, const int* in_sizes, int n_in,
                              void* d_out, int out_size)
{
    const int*   positions = (const int*)d_in[0];
    const float* hs        = (const float*)d_in[1];
    const float* w_qkv     = (const float*)d_in[2];
    const float* w_dense   = (const float*)d_in[3];
    const float* lora_in   = (const float*)d_in[4];
    const float* lora_out  = (const float*)d_in[5];
    float* out = (float*)d_out;

    const size_t N_HS = (size_t)Bb_ * S_ * HID_;
    const size_t N_WQ = (size_t)O3_ * HID_;
    const size_t N_WD = (size_t)HID_ * HID_;

    split_hs_kernel<<<(unsigned)(N_HS / 1024), 256>>>(hs);
    split_wq_kernel<<<(unsigned)(N_WQ / 1024), 256>>>(w_qkv);

    lora_mid_kernel<<<Bb_ * S_, 256>>>(hs, lora_in);

    k_qkv<<<dim3(O3_ / 128, (Bb_ * S_) / 128), 256>>>(lora_out);

    rope_kernel<<<Bb_ * S_, 256>>>(positions);

    k_scores<<<dim3(36, Bb_ * NH_), 256>>>();

    // g_k dead after k_scores: stash wd presplit there for k_dense
    split_wd_kernel<<<(unsigned)(N_WD / 1024), 256>>>(w_dense);

    softmax_kernel<<<Bb_ * NH_ * S_, 256>>>();

    k_pv<<<dim3(S_ / 128, Bb_ * NH_), 256>>>();

    k_dense<<<dim3(HID_ / 128, (Bb_ * S_) / 128), 256>>>(out);
}